// round 15
// baseline (speedup 1.0000x reference)
#include <cuda_runtime.h>
#include <cuda_bf16.h>
#include <cstdint>
#include <cstddef>

// Correlation via warp-level tensor cores (mma.sync m16n8k16 bf16, sm_100-safe).
// Per (b,h,ix): C[u,s] = sum_c A[u,c]*B[s,c],
//   A[u,c] = f1[b,c,h,2u+p], B[s,c] = f2[b,c,h2,2(s-10)+p], h2 = h+2ix-20,
//   out[u,iy] = C[u, u+iy], iy in [0,21).
// bf16 2-split (x = hi+lo): C = Ahi*Bhi + Ahi*Blo + Alo*Bhi, fp32 accumulate.
// 12 warps = (p 2) x (m-tile 6); each computes its 5 band n-tiles only.
// K chunked (KC=64, 2 chunks), smem 108KB -> 2 CTAs/SM overlap phases.
// smem tile: row = 64 bf16 = 128B = 8x16B chunks, chunk XOR-swizzled by (r&7)
// -> conflict-free STS.32 fill and conflict-free ldmatrix.

#define NTHR    384
#define PLANE   18432                    // 96*192 floats
#define KC      64
#define A_TILE  12288                    // 96*128 B
#define B_TILE  15360                    // 120*128 B
#define OFF_A(p, s)  ((p) * 2 * A_TILE + (s) * A_TILE)
#define OFF_B(p, s)  (4 * A_TILE + (p) * 2 * B_TILE + (s) * B_TILE)
#define SMEM_TOTAL   (4 * A_TILE + 4 * B_TILE)   // 110592 B

__device__ __forceinline__ uint32_t smem_u32(const void* p) {
    uint32_t a;
    asm("{ .reg .u64 t; cvta.to.shared.u64 t, %1; cvt.u32.u64 %0, t; }"
        : "=r"(a) : "l"(p));
    return a;
}

// swizzled byte offset of bf16 element (row r, col c in [0,64))
__device__ __forceinline__ uint32_t toff(int r, int c) {
    return (uint32_t)(r * 128 + ((((c >> 3) ^ (r & 7)) << 4) | ((c & 7) << 1)));
}

__device__ __forceinline__ void ldmx4(uint32_t* r, uint32_t addr) {
    asm volatile("ldmatrix.sync.aligned.m8n8.x4.shared.b16 {%0,%1,%2,%3}, [%4];"
                 : "=r"(r[0]), "=r"(r[1]), "=r"(r[2]), "=r"(r[3]) : "r"(addr));
}
__device__ __forceinline__ void ldmx2(uint32_t* r, uint32_t addr) {
    asm volatile("ldmatrix.sync.aligned.m8n8.x2.shared.b16 {%0,%1}, [%2];"
                 : "=r"(r[0]), "=r"(r[1]) : "r"(addr));
}
__device__ __forceinline__ void mma16816(float* c, const uint32_t* a, const uint32_t* b) {
    asm volatile(
        "mma.sync.aligned.m16n8k16.row.col.f32.bf16.bf16.f32 "
        "{%0,%1,%2,%3}, {%4,%5,%6,%7}, {%8,%9}, {%0,%1,%2,%3};"
        : "+f"(c[0]), "+f"(c[1]), "+f"(c[2]), "+f"(c[3])
        : "r"(a[0]), "r"(a[1]), "r"(a[2]), "r"(a[3]), "r"(b[0]), "r"(b[1]));
}

__global__ void __launch_bounds__(NTHR, 2)
corr_mma_kernel(const float* __restrict__ f1, const float* __restrict__ f2,
                float* __restrict__ out)
{
    extern __shared__ char smem[];
    const int h  = blockIdx.x;    // 0..95
    const int ix = blockIdx.y;    // 0..20
    const int b  = blockIdx.z;    // 0..3
    const int tid = threadIdx.x;
    const int wid = tid / 32;
    const int l   = tid % 32;
    const int h2  = h + 2 * ix - 20;

    // OOB window row: whole (b, ix, h) output slice is zero (pad semantics)
    if ((unsigned)h2 >= 96u) {
        size_t base = (((size_t)b * 441 + (size_t)ix * 21) * 96 + h) * 192;
        float4 z = make_float4(0.f, 0.f, 0.f, 0.f);
        for (int i = tid; i < 21 * 48; i += NTHR) {
            int iy = i / 48, w4 = i % 48;
            *reinterpret_cast<float4*>(out + base + (size_t)iy * PLANE + 4 * w4) = z;
        }
        return;
    }

    const uint32_t sb = smem_u32(smem);

    // zero B pad rows (s<10, s>105) across all 4 B tiles, once (persists: fill
    // never writes them, single-buffered chunks reuse the same rows)
    for (int it = 0; it < 2; it++) {
        int idx = tid + it * NTHR;           // 768 float4 rows-chunks total
        int rowidx = idx >> 3, f4 = idx & 7;
        int tile = rowidx / 24, rr = rowidx % 24;
        int r = (rr < 10) ? rr : (rr + 96);  // 0..9 or 106..119
        float4* dst = reinterpret_cast<float4*>(
            smem + 4 * A_TILE + tile * B_TILE + r * 128 + f4 * 16);
        *dst = make_float4(0.f, 0.f, 0.f, 0.f);
    }
    __syncthreads();

    // warp role for MMA: parity p, m-tile mi
    const int wp = wid / 6;            // 0..1
    const int mi = wid % 6;            // 0..5, u0 = 16*mi
    const int u0 = 16 * mi;

    float acc[5][4];
    #pragma unroll
    for (int i = 0; i < 5; i++)
        #pragma unroll
        for (int e = 0; e < 4; e++) acc[i][e] = 0.f;

    // per-lane ldmatrix row constants
    const int rA  = u0 + (l & 7) + 8 * ((l >> 3) & 1);   // A row for this lane
    const uint32_t rAb = (uint32_t)(rA * 128);
    const int xA  = rA & 7;
    const int cbA = l >> 4;                               // 0 or 1 (k-halves)
    const int lB7 = l & 7;
    const int cbB = (l >> 3) & 1;

    const uint32_t a_hi = sb + OFF_A(wp, 0), a_lo = sb + OFF_A(wp, 1);
    const uint32_t b_hi = sb + OFF_B(wp, 0), b_lo = sb + OFF_B(wp, 1);

    #pragma unroll 1
    for (int ck = 0; ck < 2; ck++) {
        // ---- fill chunk ck: c in [64ck, 64ck+64) ----
        {
            const int c0 = 64 * ck;
            const int du = l & 7, dcp = l >> 3;
            #pragma unroll 1
            for (int blk = wid; blk < 192; blk += 12) {
                int tb   = blk < 96 ? 0 : 1;            // 0 = f1, 1 = f2
                int bb   = blk - tb * 96;
                int ublk = bb % 12, cblk = bb / 12;
                int row  = ublk * 8 + du;               // u (f1) or s-10 (f2)
                int cl   = cblk * 8 + 2 * dcp;          // local c (even)
                int c    = c0 + cl;
                int srow, wg, hrow;
                const float* src;
                uint32_t base0, base1;                  // hi/lo tile bases (p=0)
                if (tb == 0) {
                    srow = row; hrow = h; wg = 2 * row; src = f1;
                    base0 = sb + OFF_A(0, 0); base1 = sb + OFF_A(0, 1);
                } else {
                    srow = row + 10; hrow = h2; wg = 2 * row; src = f2;
                    base0 = sb + OFF_B(0, 0); base1 = sb + OFF_B(0, 1);
                }
                size_t g = ((size_t)(b * 128 + c) * 96 + hrow) * 192 + wg;
                float2 v0 = *reinterpret_cast<const float2*>(src + g);
                float2 v1 = *reinterpret_cast<const float2*>(src + g + PLANE);
                uint32_t off = toff(srow, cl);
                // parity 0 (x components)
                __nv_bfloat162 h2a = __floats2bfloat162_rn(v0.x, v1.x);
                __nv_bfloat162 l2a = __floats2bfloat162_rn(
                    v0.x - __low2float(h2a), v1.x - __high2float(h2a));
                *reinterpret_cast<uint32_t*>(smem + (base0 - sb) + off) =
                    *reinterpret_cast<uint32_t*>(&h2a);
                *reinterpret_cast<uint32_t*>(smem + (base1 - sb) + off) =
                    *reinterpret_cast<uint32_t*>(&l2a);
                // parity 1 (y components)
                uint32_t pd = (tb == 0) ? (uint32_t)(2 * A_TILE) : (uint32_t)(2 * B_TILE);
                __nv_bfloat162 h2b = __floats2bfloat162_rn(v0.y, v1.y);
                __nv_bfloat162 l2b = __floats2bfloat162_rn(
                    v0.y - __low2float(h2b), v1.y - __high2float(h2b));
                *reinterpret_cast<uint32_t*>(smem + (base0 - sb) + pd + off) =
                    *reinterpret_cast<uint32_t*>(&h2b);
                *reinterpret_cast<uint32_t*>(smem + (base1 - sb) + pd + off) =
                    *reinterpret_cast<uint32_t*>(&l2b);
            }
        }
        __syncthreads();

        // ---- MMA on chunk: 4 k16 steps ----
        #pragma unroll
        for (int kk = 0; kk < 4; kk++) {
            uint32_t ah[4], al[4];
            uint32_t aoff = rAb + (uint32_t)((((2 * kk + cbA) ^ xA) << 4));
            ldmx4(ah, a_hi + aoff);
            ldmx4(al, a_lo + aoff);
            #pragma unroll
            for (int ni = 0; ni < 5; ni++) {
                int sB = 8 * (2 * mi + ni) + lB7;
                uint32_t boff = (uint32_t)(sB * 128 + (((2 * kk + cbB) ^ (sB & 7)) << 4));
                uint32_t bh[2], bl[2];
                ldmx2(bh, b_hi + boff);
                ldmx2(bl, b_lo + boff);
                mma16816(acc[ni], ah, bh);
                mma16816(acc[ni], ah, bl);
                mma16816(acc[ni], al, bh);
            }
        }
        if (ck == 0) __syncthreads();   // before refill overwrites tiles
    }

    // ---- epilogue: extract band, scattered STG.32 ----
    {
        size_t obase = (((size_t)b * 441 + (size_t)ix * 21) * 96 + h) * 192 + wp;
        #pragma unroll
        for (int ni = 0; ni < 5; ni++) {
            #pragma unroll
            for (int e = 0; e < 4; e++) {
                int r = u0 + (l >> 2) + 8 * (e >> 1);
                int s = 8 * (2 * mi + ni) + 2 * (l & 3) + (e & 1);
                int iy = s - r;
                if ((unsigned)iy < 21u)
                    out[obase + (size_t)iy * PLANE + 2 * r] = acc[ni][e];
            }
        }
    }
}

extern "C" void kernel_launch(void* const* d_in, const int* in_sizes, int n_in,
                              void* d_out, int out_size)
{
    const float* f1 = (const float*)d_in[0];
    const float* f2 = (const float*)d_in[1];
    float* out = (float*)d_out;

    cudaFuncSetAttribute(corr_mma_kernel, cudaFuncAttributeMaxDynamicSharedMemorySize,
                         SMEM_TOTAL);
    dim3 grid(96, 21, 4);   // (h, ix, b)
    corr_mma_kernel<<<grid, NTHR, SMEM_TOTAL>>>(f1, f2, out);
}

// round 16
// speedup vs baseline: 1.1487x; 1.1487x over previous
#include <cuda_runtime.h>
#include <cuda_bf16.h>
#include <cstdint>
#include <cstddef>

// Correlation via mma.sync (m16n8k16 bf16, sm_100-safe), two-phase:
//   prepass: fp32 -> bf16 hi/lo split, transposed to GEMM rows [b][h][p][u][c]
//            (done ONCE; R15 redid this conversion in all 21 ix-CTAs per plane)
//   main:    per (b,h,ix): C[u,s] = sum_c A[u,c]*B[s,c], band epilogue
//            out[u,iy] = C[u,u+iy]. Fill = pure LDG.128->STS.128 copy.
// C = Ahi*Bhi + Ahi*Blo + Alo*Bhi (fp32 accum), rel_err ~5e-6.

#define NTHR    384
#define PLANE   18432                    // 96*192 floats
#define A_TILE  12288                    // 96 rows * 128B
#define B_TILE  15360                    // 120 rows * 128B
#define OFF_A(p, s)  ((p) * 2 * A_TILE + (s) * A_TILE)
#define OFF_B(p, s)  (4 * A_TILE + (p) * 2 * B_TILE + (s) * B_TILE)
#define SMEM_TOTAL   (4 * A_TILE + 4 * B_TILE)   // 110592 B

#define SCR_ROWS (4 * 96 * 2 * 96)       // b,h,p,u rows of 128 bf16
__device__ __nv_bfloat16 g_f1hi[SCR_ROWS * 128];
__device__ __nv_bfloat16 g_f1lo[SCR_ROWS * 128];
__device__ __nv_bfloat16 g_f2hi[SCR_ROWS * 128];
__device__ __nv_bfloat16 g_f2lo[SCR_ROWS * 128];

__device__ __forceinline__ uint32_t smem_u32(const void* p) {
    uint32_t a;
    asm("{ .reg .u64 t; cvta.to.shared.u64 t, %1; cvt.u32.u64 %0, t; }"
        : "=r"(a) : "l"(p));
    return a;
}
__device__ __forceinline__ void ldmx4(uint32_t* r, uint32_t addr) {
    asm volatile("ldmatrix.sync.aligned.m8n8.x4.shared.b16 {%0,%1,%2,%3}, [%4];"
                 : "=r"(r[0]), "=r"(r[1]), "=r"(r[2]), "=r"(r[3]) : "r"(addr));
}
__device__ __forceinline__ void ldmx2(uint32_t* r, uint32_t addr) {
    asm volatile("ldmatrix.sync.aligned.m8n8.x2.shared.b16 {%0,%1}, [%2];"
                 : "=r"(r[0]), "=r"(r[1]) : "r"(addr));
}
__device__ __forceinline__ void mma16816(float* c, const uint32_t* a, const uint32_t* b) {
    asm volatile(
        "mma.sync.aligned.m16n8k16.row.col.f32.bf16.bf16.f32 "
        "{%0,%1,%2,%3}, {%4,%5,%6,%7}, {%8,%9}, {%0,%1,%2,%3};"
        : "+f"(c[0]), "+f"(c[1]), "+f"(c[2]), "+f"(c[3])
        : "r"(a[0]), "r"(a[1]), "r"(a[2]), "r"(a[3]), "r"(b[0]), "r"(b[1]));
}

// ---------------- prepass: convert + transpose ----------------
__global__ void __launch_bounds__(256)
prep_kernel(const float* __restrict__ f1, const float* __restrict__ f2)
{
    __shared__ float sm[32 * 192];
    const int h = blockIdx.x, b = blockIdx.y, t = blockIdx.z;
    const int tid = threadIdx.x;
    const float* src = t ? f2 : f1;
    __nv_bfloat16* dhi = t ? g_f2hi : g_f1hi;
    __nv_bfloat16* dlo = t ? g_f2lo : g_f1lo;
    const int rb = (b * 96 + h) * 2 * 96;      // row base for (b,h,p=0,u=0)

    #pragma unroll 1
    for (int slab = 0; slab < 4; slab++) {
        const int c0 = 32 * slab;
        // load 32 channels x 192 w (coalesced float4)
        #pragma unroll
        for (int it = 0; it < 6; it++) {
            int idx = tid + it * 256;          // < 1536
            int cc = idx / 48, w4 = idx % 48;
            *reinterpret_cast<float4*>(sm + cc * 192 + 4 * w4) =
                *reinterpret_cast<const float4*>(
                    src + ((size_t)(b * 128 + c0 + cc) * 96 + h) * 192 + 4 * w4);
        }
        __syncthreads();
        // convert/split/store transposed: (p,u,cc)
        #pragma unroll
        for (int it = 0; it < 24; it++) {
            int idx = tid + it * 256;          // < 6144
            int cc = idx & 31;
            int r2 = idx >> 5;
            int u  = r2 % 96;
            int p  = r2 / 96;
            float x = sm[cc * 192 + 2 * u + p];
            __nv_bfloat16 hi = __float2bfloat16_rn(x);
            __nv_bfloat16 lo = __float2bfloat16_rn(x - __bfloat162float(hi));
            size_t off = (size_t)(rb + p * 96 + u) * 128 + c0 + cc;
            dhi[off] = hi;
            dlo[off] = lo;
        }
        __syncthreads();
    }
}

// ---------------- main: copy-fill + banded MMA ----------------
__global__ void __launch_bounds__(NTHR, 2)
corr_mma_kernel(const float* __restrict__ f1, const float* __restrict__ f2,
                float* __restrict__ out)
{
    extern __shared__ char smem[];
    const int h  = blockIdx.x;    // 0..95
    const int ix = blockIdx.y;    // 0..20
    const int b  = blockIdx.z;    // 0..3
    const int tid = threadIdx.x;
    const int wid = tid / 32;
    const int l   = tid % 32;
    const int h2  = h + 2 * ix - 20;

    if ((unsigned)h2 >= 96u) {    // OOB window row -> zero slice
        size_t base = (((size_t)b * 441 + (size_t)ix * 21) * 96 + h) * 192;
        float4 z = make_float4(0.f, 0.f, 0.f, 0.f);
        for (int i = tid; i < 21 * 48; i += NTHR) {
            int iy = i / 48, w4 = i % 48;
            *reinterpret_cast<float4*>(out + base + (size_t)iy * PLANE + 4 * w4) = z;
        }
        return;
    }

    const uint32_t sb = smem_u32(smem);

    // zero B pad rows (s<10, s>105) across all 4 B tiles, once
    for (int it = 0; it < 2; it++) {
        int idx = tid + it * NTHR;
        int rowidx = idx >> 3, f4 = idx & 7;
        int tile = rowidx / 24, rr = rowidx % 24;
        int r = (rr < 10) ? rr : (rr + 96);
        *reinterpret_cast<float4*>(smem + 4 * A_TILE + tile * B_TILE + r * 128 + f4 * 16)
            = make_float4(0.f, 0.f, 0.f, 0.f);
    }
    __syncthreads();

    const int wp = wid / 6;            // parity
    const int mi = wid % 6;            // m-tile, u0 = 16*mi
    const int u0 = 16 * mi;

    float acc[5][4];
    #pragma unroll
    for (int i = 0; i < 5; i++)
        #pragma unroll
        for (int e = 0; e < 4; e++) acc[i][e] = 0.f;

    const int rA  = u0 + (l & 7) + 8 * ((l >> 3) & 1);
    const uint32_t rAb = (uint32_t)(rA * 128);
    const int xA  = rA & 7;
    const int cbA = l >> 4;
    const int lB7 = l & 7;
    const int cbB = (l >> 3) & 1;

    const uint32_t a_hi = sb + OFF_A(wp, 0), a_lo = sb + OFF_A(wp, 1);
    const uint32_t b_hi = sb + OFF_B(wp, 0), b_lo = sb + OFF_B(wp, 1);

    const int rb1 = (b * 96 + h)  * 2 * 96;   // f1 scratch row base
    const int rb2 = (b * 96 + h2) * 2 * 96;   // f2 scratch row base

    #pragma unroll 1
    for (int ck = 0; ck < 2; ck++) {
        const int cko = 64 * ck;               // bf16 element offset in row
        // ---- copy-fill chunk: A = 3072 16B chunks, B = 3072 ----
        #pragma unroll
        for (int i = 0; i < 8; i++) {          // A
            int idx = tid + i * NTHR;
            int j  = idx & 7;
            int u  = (idx >> 3) % 96;
            int r2 = (idx >> 3) / 96;          // bit0 = hi/lo, bit1 = p
            int hl = r2 & 1, p = r2 >> 1;
            const __nv_bfloat16* src = hl ? g_f1lo : g_f1hi;
            uint4 v = *reinterpret_cast<const uint4*>(
                src + (size_t)(rb1 + p * 96 + u) * 128 + cko + 8 * j);
            *reinterpret_cast<uint4*>(smem + OFF_A(p, hl)
                + u * 128 + (((j ^ (u & 7)) << 4))) = v;
        }
        #pragma unroll
        for (int i = 0; i < 8; i++) {          // B (dest rows s = u'+10)
            int idx = tid + i * NTHR;
            int j  = idx & 7;
            int u  = (idx >> 3) % 96;
            int r2 = (idx >> 3) / 96;
            int hl = r2 & 1, p = r2 >> 1;
            const __nv_bfloat16* src = hl ? g_f2lo : g_f2hi;
            uint4 v = *reinterpret_cast<const uint4*>(
                src + (size_t)(rb2 + p * 96 + u) * 128 + cko + 8 * j);
            int s = u + 10;
            *reinterpret_cast<uint4*>(smem + OFF_B(p, hl)
                + s * 128 + (((j ^ (s & 7)) << 4))) = v;
        }
        __syncthreads();

        // ---- MMA on chunk: 4 k16 steps ----
        #pragma unroll
        for (int kk = 0; kk < 4; kk++) {
            uint32_t ah[4], al[4];
            uint32_t aoff = rAb + (uint32_t)((((2 * kk + cbA) ^ xA) << 4));
            ldmx4(ah, a_hi + aoff);
            ldmx4(al, a_lo + aoff);
            #pragma unroll
            for (int ni = 0; ni < 5; ni++) {
                int sB = 8 * (2 * mi + ni) + lB7;
                uint32_t boff = (uint32_t)(sB * 128 + (((2 * kk + cbB) ^ (sB & 7)) << 4));
                uint32_t bh[2], bl[2];
                ldmx2(bh, b_hi + boff);
                ldmx2(bl, b_lo + boff);
                mma16816(acc[ni], ah, bh);
                mma16816(acc[ni], ah, bl);
                mma16816(acc[ni], al, bh);
            }
        }
        if (ck == 0) __syncthreads();
    }

    // ---- epilogue: band extraction ----
    {
        size_t obase = (((size_t)b * 441 + (size_t)ix * 21) * 96 + h) * 192 + wp;
        #pragma unroll
        for (int ni = 0; ni < 5; ni++) {
            #pragma unroll
            for (int e = 0; e < 4; e++) {
                int r = u0 + (l >> 2) + 8 * (e >> 1);
                int s = 8 * (2 * mi + ni) + 2 * (l & 3) + (e & 1);
                int iy = s - r;
                if ((unsigned)iy < 21u)
                    out[obase + (size_t)iy * PLANE + 2 * r] = acc[ni][e];
            }
        }
    }
}

extern "C" void kernel_launch(void* const* d_in, const int* in_sizes, int n_in,
                              void* d_out, int out_size)
{
    const float* f1 = (const float*)d_in[0];
    const float* f2 = (const float*)d_in[1];
    float* out = (float*)d_out;

    dim3 pgrid(96, 4, 2);
    prep_kernel<<<pgrid, 256>>>(f1, f2);

    cudaFuncSetAttribute(corr_mma_kernel, cudaFuncAttributeMaxDynamicSharedMemorySize,
                         SMEM_TOTAL);
    dim3 grid(96, 21, 4);   // (h, ix, b)
    corr_mma_kernel<<<grid, NTHR, SMEM_TOTAL>>>(f1, f2, out);
}

// round 17
// speedup vs baseline: 1.6972x; 1.4775x over previous
#include <cuda_runtime.h>
#include <cuda_bf16.h>
#include <cstdint>
#include <cstddef>

// Correlation via mma.sync (m16n8k16 bf16), two-phase:
//   prepass: fp32 -> bf16 hi/lo split, transposed to rows [b][h][p][u][c0..127]
//   main: per (b,h,ix): C[u,s] = sum_c A[u,c]*B[s,c]; out[u,iy] = C[u,u+iy].
// C = Ahi*Bhi + Ahi*Blo + Alo*Bhi (fp32 accum), rel_err ~5e-6.
// R17: prepass bank-conflict fix (stride 193); fill via cp.async.cg (no RF
// round trip); B hi/lo ldmatrix merged into x4; band epilogue staged through
// smem (stride 99) for coalesced global writes.

#define NTHR    384
#define PLANE   18432                    // 96*192 floats
#define A_TILE  12288                    // 96 rows * 128B
#define B_TILE  15360                    // 120 rows * 128B
#define OFF_A(p, s)  ((p) * 2 * A_TILE + (s) * A_TILE)
#define OFF_B(p, s)  (4 * A_TILE + (p) * 2 * B_TILE + (s) * B_TILE)
#define SMEM_TOTAL   (4 * A_TILE + 4 * B_TILE)   // 110592 B
#define SO_P    2080                     // epilogue slab stride (floats) per parity

#define SCR_ROWS (4 * 96 * 2 * 96)       // b,h,p,u rows of 128 bf16
__device__ __nv_bfloat16 g_f1hi[SCR_ROWS * 128];
__device__ __nv_bfloat16 g_f1lo[SCR_ROWS * 128];
__device__ __nv_bfloat16 g_f2hi[SCR_ROWS * 128];
__device__ __nv_bfloat16 g_f2lo[SCR_ROWS * 128];

__device__ __forceinline__ uint32_t smem_u32(const void* p) {
    uint32_t a;
    asm("{ .reg .u64 t; cvta.to.shared.u64 t, %1; cvt.u32.u64 %0, t; }"
        : "=r"(a) : "l"(p));
    return a;
}
__device__ __forceinline__ void cp16(uint32_t dst, const void* src) {
    asm volatile("cp.async.cg.shared.global [%0], [%1], 16;" :: "r"(dst), "l"(src));
}
__device__ __forceinline__ void ldmx4(uint32_t* r, uint32_t addr) {
    asm volatile("ldmatrix.sync.aligned.m8n8.x4.shared.b16 {%0,%1,%2,%3}, [%4];"
                 : "=r"(r[0]), "=r"(r[1]), "=r"(r[2]), "=r"(r[3]) : "r"(addr));
}
__device__ __forceinline__ void mma16816(float* c, const uint32_t* a, const uint32_t* b) {
    asm volatile(
        "mma.sync.aligned.m16n8k16.row.col.f32.bf16.bf16.f32 "
        "{%0,%1,%2,%3}, {%4,%5,%6,%7}, {%8,%9}, {%0,%1,%2,%3};"
        : "+f"(c[0]), "+f"(c[1]), "+f"(c[2]), "+f"(c[3])
        : "r"(a[0]), "r"(a[1]), "r"(a[2]), "r"(a[3]), "r"(b[0]), "r"(b[1]));
}

// ---------------- prepass: convert + transpose (conflict-free) ----------------
__global__ void __launch_bounds__(256)
prep_kernel(const float* __restrict__ f1, const float* __restrict__ f2)
{
    __shared__ float sm[32 * 193];
    const int h = blockIdx.x, b = blockIdx.y, t = blockIdx.z;
    const int tid = threadIdx.x;
    const float* src = t ? f2 : f1;
    __nv_bfloat16* dhi = t ? g_f2hi : g_f1hi;
    __nv_bfloat16* dlo = t ? g_f2lo : g_f1lo;
    const int rb = (b * 96 + h) * 2 * 96;

    #pragma unroll 1
    for (int slab = 0; slab < 4; slab++) {
        const int c0 = 32 * slab;
        #pragma unroll
        for (int it = 0; it < 24; it++) {      // coalesced scalar loads
            int idx = tid + it * 256;          // < 6144
            int cc = idx / 192, w = idx - cc * 192;
            sm[cc * 193 + w] =
                src[((size_t)(b * 128 + c0 + cc) * 96 + h) * 192 + w];
        }
        __syncthreads();
        #pragma unroll
        for (int it = 0; it < 24; it++) {      // conflict-free strided reads
            int idx = tid + it * 256;          // (p, u, cc)
            int cc = idx & 31;
            int r2 = idx >> 5;                 // warp-uniform
            int u  = r2 % 96, p = r2 / 96;
            float x = sm[cc * 193 + 2 * u + p];
            __nv_bfloat16 hi = __float2bfloat16_rn(x);
            __nv_bfloat16 lo = __float2bfloat16_rn(x - __bfloat162float(hi));
            size_t off = (size_t)(rb + p * 96 + u) * 128 + c0 + cc;
            dhi[off] = hi;
            dlo[off] = lo;
        }
        __syncthreads();
    }
}

// ---------------- main: cp.async fill + banded MMA + staged epilogue ----------
__global__ void __launch_bounds__(NTHR, 2)
corr_mma_kernel(const float* __restrict__ f1, const float* __restrict__ f2,
                float* __restrict__ out)
{
    extern __shared__ char smem[];
    const int h  = blockIdx.x;
    const int ix = blockIdx.y;
    const int b  = blockIdx.z;
    const int tid = threadIdx.x;
    const int wid = tid / 32;
    const int l   = tid % 32;
    const int h2  = h + 2 * ix - 20;

    if ((unsigned)h2 >= 96u) {    // OOB window row -> zero slice
        size_t base = (((size_t)b * 441 + (size_t)ix * 21) * 96 + h) * 192;
        float4 z = make_float4(0.f, 0.f, 0.f, 0.f);
        for (int i = tid; i < 21 * 48; i += NTHR) {
            int iy = i / 48, w4 = i % 48;
            *reinterpret_cast<float4*>(out + base + (size_t)iy * PLANE + 4 * w4) = z;
        }
        return;
    }

    const uint32_t sb = smem_u32(smem);

    // zero B pad rows (s<10, s>105) across all 4 B tiles, once
    for (int it = 0; it < 2; it++) {
        int idx = tid + it * NTHR;
        int rowidx = idx >> 3, f4 = idx & 7;
        int tile = rowidx / 24, rr = rowidx % 24;
        int r = (rr < 10) ? rr : (rr + 96);
        *reinterpret_cast<float4*>(smem + 4 * A_TILE + tile * B_TILE + r * 128 + f4 * 16)
            = make_float4(0.f, 0.f, 0.f, 0.f);
    }
    __syncthreads();

    const int wp = wid / 6;            // parity
    const int mi = wid % 6;            // m-tile, u0 = 16*mi
    const int u0 = 16 * mi;

    float acc[5][4];
    #pragma unroll
    for (int i = 0; i < 5; i++)
        #pragma unroll
        for (int e = 0; e < 4; e++) acc[i][e] = 0.f;

    const int rA  = u0 + (l & 7) + 8 * ((l >> 3) & 1);
    const uint32_t rAb = (uint32_t)(rA * 128);
    const int xA  = rA & 7;
    const int cbA = l >> 4;
    const int l7  = l & 7;
    const int khb = (l >> 3) & 1;

    const uint32_t a_hi = sb + OFF_A(wp, 0), a_lo = sb + OFF_A(wp, 1);
    // merged B x4 base: lanes 0-15 -> b_hi, 16-31 -> b_lo; row = 16*mi + l7
    const uint32_t bbase0 = sb + OFF_B(wp, 0) + (uint32_t)((l >> 4) * B_TILE)
                          + (uint32_t)((16 * mi + l7) * 128);

    const int rb1 = (b * 96 + h)  * 2 * 96;
    const int rb2 = (b * 96 + h2) * 2 * 96;

    #pragma unroll 1
    for (int ck = 0; ck < 2; ck++) {
        const int cko = 64 * ck;
        // ---- cp.async fill: A (3072 16B segs) + B (3072) ----
        #pragma unroll
        for (int i = 0; i < 8; i++) {
            int idx = tid + i * NTHR;
            int j  = idx & 7;
            int u  = (idx >> 3) % 96;
            int r2 = (idx >> 3) / 96;
            int hl = r2 & 1, p = r2 >> 1;
            const __nv_bfloat16* src = hl ? g_f1lo : g_f1hi;
            cp16(sb + OFF_A(p, hl) + u * 128 + (((j ^ (u & 7)) << 4)),
                 src + (size_t)(rb1 + p * 96 + u) * 128 + cko + 8 * j);
        }
        #pragma unroll
        for (int i = 0; i < 8; i++) {
            int idx = tid + i * NTHR;
            int j  = idx & 7;
            int u  = (idx >> 3) % 96;
            int r2 = (idx >> 3) / 96;
            int hl = r2 & 1, p = r2 >> 1;
            const __nv_bfloat16* src = hl ? g_f2lo : g_f2hi;
            int s = u + 10;
            cp16(sb + OFF_B(p, hl) + s * 128 + (((j ^ (s & 7)) << 4)),
                 src + (size_t)(rb2 + p * 96 + u) * 128 + cko + 8 * j);
        }
        asm volatile("cp.async.commit_group;");
        asm volatile("cp.async.wait_group 0;" ::: "memory");
        __syncthreads();

        // ---- MMA on chunk: 4 k16 steps ----
        #pragma unroll
        for (int kk = 0; kk < 4; kk++) {
            uint32_t ah[4], al[4];
            uint32_t aoff = rAb + (uint32_t)((((2 * kk + cbA) ^ xA) << 4));
            ldmx4(ah, a_hi + aoff);
            ldmx4(al, a_lo + aoff);
            uint32_t baddr = bbase0 + (uint32_t)((((2 * kk + khb) ^ l7) << 4));
            #pragma unroll
            for (int ni = 0; ni < 5; ni++) {
                uint32_t bb[4];                   // bb[0..1]=bhi, bb[2..3]=blo
                ldmx4(bb, baddr);
                baddr += 1024;                    // next n-tile (8 rows)
                mma16816(acc[ni], ah, bb);
                mma16816(acc[ni], ah, bb + 2);
                mma16816(acc[ni], al, bb);
            }
        }
        __syncthreads();   // ck0: before refill; ck1: before epilogue overwrite
    }

    // ---- epilogue: band -> smem (A region, now dead) -> coalesced STG ----
    {
        float* so = reinterpret_cast<float*>(smem);   // [p][iy*99 + r]
        #pragma unroll
        for (int ni = 0; ni < 5; ni++) {
            #pragma unroll
            for (int e = 0; e < 4; e++) {
                int r = u0 + (l >> 2) + 8 * (e >> 1);
                int s = 8 * (2 * mi + ni) + 2 * (l & 3) + (e & 1);
                int iy = s - r;
                if ((unsigned)iy < 21u)
                    so[wp * SO_P + iy * 99 + r] = acc[ni][e];
            }
        }
        __syncthreads();
        size_t obase = (((size_t)b * 441 + (size_t)ix * 21) * 96 + h) * 192;
        #pragma unroll
        for (int it = 0; it < 11; it++) {
            int idx = tid + it * NTHR;
            if (idx < 21 * 192) {
                int iy = idx / 192, w = idx - iy * 192;
                out[obase + (size_t)iy * PLANE + w] =
                    so[(w & 1) * SO_P + iy * 99 + (w >> 1)];
            }
        }
    }
}

extern "C" void kernel_launch(void* const* d_in, const int* in_sizes, int n_in,
                              void* d_out, int out_size)
{
    const float* f1 = (const float*)d_in[0];
    const float* f2 = (const float*)d_in[1];
    float* out = (float*)d_out;

    dim3 pgrid(96, 4, 2);
    prep_kernel<<<pgrid, 256>>>(f1, f2);

    cudaFuncSetAttribute(corr_mma_kernel, cudaFuncAttributeMaxDynamicSharedMemorySize,
                         SMEM_TOTAL);
    dim3 grid(96, 21, 4);   // (h, ix, b)
    corr_mma_kernel<<<grid, NTHR, SMEM_TOTAL>>>(f1, f2, out);
}